// round 1
// baseline (speedup 1.0000x reference)
#include <cuda_runtime.h>
#include <cuda_bf16.h>
#include <cstdint>

// Problem constants
#define BATCH 2
#define HH 96
#define WW 96
#define CC 128
#define KD 64
#define OD 128
#define KS 7
#define PADW 3
#define NPIX (BATCH * HH * WW)   // 18432

// Scratch (allocation-free rule: __device__ globals)
__device__ float g_q[NPIX * KD];
__device__ float g_k[NPIX * KD];
__device__ float g_attn[NPIX * OD];

// ---------------------------------------------------------------------------
// Generic tiled GEMM: C[M,N] = A[M,128] @ W[128,N] + bias, optional relu.
// BM=64 rows per block, 256 threads, full K=128 staged in smem.
// Thread (ty,tx) with ty=t/16, tx=t%16 computes rows ty*4..+3, cols tx*TN..+TN-1.
// ---------------------------------------------------------------------------
template <int N, bool RELU>
__global__ void gemm128_kernel(const float* __restrict__ A,
                               const float* __restrict__ Wt,
                               const float* __restrict__ bias,
                               float* __restrict__ C)
{
    extern __shared__ float sm[];
    float* As = sm;             // [64][129]  (pad 129 -> conflict-free column reads)
    float* Ws = As + 64 * 129;  // [128][N]

    const int m0 = blockIdx.x * 64;
    const int t  = threadIdx.x;

    // Load A tile: 64 rows x 128 cols = 2048 float4, coalesced
    for (int i = t; i < 2048; i += 256) {
        int r = i >> 5;         // /32 float4 per row
        int c4 = i & 31;
        float4 v = *reinterpret_cast<const float4*>(A + (size_t)(m0 + r) * 128 + c4 * 4);
        float* d = As + r * 129 + c4 * 4;
        d[0] = v.x; d[1] = v.y; d[2] = v.z; d[3] = v.w;
    }
    // Load W: 128 x N floats, straight copy
    for (int i = t; i < 128 * N / 4; i += 256) {
        *reinterpret_cast<float4*>(Ws + i * 4) =
            *reinterpret_cast<const float4*>(Wt + i * 4);
    }
    __syncthreads();

    constexpr int TN = N / 16;  // 4 (N=64) or 8 (N=128)
    const int ty = t >> 4;      // 0..15
    const int tx = t & 15;      // 0..15

    float acc[4][TN];
#pragma unroll
    for (int i = 0; i < 4; i++)
#pragma unroll
        for (int j = 0; j < TN; j++) acc[i][j] = 0.0f;

#pragma unroll 8
    for (int kk = 0; kk < 128; kk++) {
        float a[4];
#pragma unroll
        for (int i = 0; i < 4; i++) a[i] = As[(ty * 4 + i) * 129 + kk];
        float w[TN];
#pragma unroll
        for (int j4 = 0; j4 < TN / 4; j4++) {
            float4 wv = *reinterpret_cast<const float4*>(Ws + kk * N + tx * TN + j4 * 4);
            w[j4 * 4 + 0] = wv.x; w[j4 * 4 + 1] = wv.y;
            w[j4 * 4 + 2] = wv.z; w[j4 * 4 + 3] = wv.w;
        }
#pragma unroll
        for (int i = 0; i < 4; i++)
#pragma unroll
            for (int j = 0; j < TN; j++)
                acc[i][j] = fmaf(a[i], w[j], acc[i][j]);
    }

    // Epilogue: bias (+relu), float4 stores
#pragma unroll
    for (int i = 0; i < 4; i++) {
        int row = m0 + ty * 4 + i;
#pragma unroll
        for (int j4 = 0; j4 < TN / 4; j4++) {
            int cb = tx * TN + j4 * 4;
            float4 o;
            o.x = acc[i][j4 * 4 + 0] + bias[cb + 0];
            o.y = acc[i][j4 * 4 + 1] + bias[cb + 1];
            o.z = acc[i][j4 * 4 + 2] + bias[cb + 2];
            o.w = acc[i][j4 * 4 + 3] + bias[cb + 3];
            if (RELU) {
                o.x = fmaxf(o.x, 0.0f); o.y = fmaxf(o.y, 0.0f);
                o.z = fmaxf(o.z, 0.0f); o.w = fmaxf(o.w, 0.0f);
            }
            *reinterpret_cast<float4*>(C + (size_t)row * N + cb) = o;
        }
    }
}

// ---------------------------------------------------------------------------
// Neighborhood attention: 8x8 pixel tile per block, 256 threads.
// smem: q tile [64][65], k halo [196][65], V halo [196][132], scores [64][52].
// ---------------------------------------------------------------------------
#define TS 8
#define WIN 14                // TS + KS - 1
#define SQ_STRIDE 65
#define SK_STRIDE 65
#define SV_STRIDE 132
#define SW_STRIDE 52

#define SMEM_ATTN_FLOATS (64 * SQ_STRIDE + 196 * SK_STRIDE + 196 * SV_STRIDE + 64 * SW_STRIDE)

__global__ void attn_kernel(const float* __restrict__ qbuf,
                            const float* __restrict__ kbuf,
                            const float* __restrict__ V,
                            float* __restrict__ out)
{
    extern __shared__ float sm[];
    float* sq = sm;                         // [64][65]
    float* sk = sq + 64 * SQ_STRIDE;        // [196][65]
    float* sv = sk + 196 * SK_STRIDE;       // [196][132]
    float* sw = sv + 196 * SV_STRIDE;       // [64][52]

    const int b   = blockIdx.z;
    const int ty0 = blockIdx.y * TS;
    const int tx0 = blockIdx.x * TS;
    const int t   = threadIdx.x;

    // ---- Phase 1: cooperative loads ----
    // q tile: 64 pixels x 16 float4
    for (int i = t; i < 64 * 16; i += 256) {
        int p = i >> 4, c4 = i & 15;
        int py = ty0 + (p >> 3), px = tx0 + (p & 7);
        float4 v = *reinterpret_cast<const float4*>(
            qbuf + ((size_t)(b * HH + py) * WW + px) * KD + c4 * 4);
        float* d = sq + p * SQ_STRIDE + c4 * 4;
        d[0] = v.x; d[1] = v.y; d[2] = v.z; d[3] = v.w;
    }
    // k halo: 196 rows x 16 float4 (OOB -> 0)
    for (int i = t; i < 196 * 16; i += 256) {
        int r = i >> 4, c4 = i & 15;
        int gy = ty0 - PADW + r / WIN;
        int gx = tx0 - PADW + r % WIN;
        float4 v = make_float4(0.f, 0.f, 0.f, 0.f);
        if (gy >= 0 && gy < HH && gx >= 0 && gx < WW)
            v = *reinterpret_cast<const float4*>(
                kbuf + ((size_t)(b * HH + gy) * WW + gx) * KD + c4 * 4);
        float* d = sk + r * SK_STRIDE + c4 * 4;
        d[0] = v.x; d[1] = v.y; d[2] = v.z; d[3] = v.w;
    }
    // V halo: 196 rows x 32 float4 (OOB -> 0); sv rows 16B-aligned (132*4=528=33*16)
    for (int i = t; i < 196 * 32; i += 256) {
        int r = i >> 5, c4 = i & 31;
        int gy = ty0 - PADW + r / WIN;
        int gx = tx0 - PADW + r % WIN;
        float4 v = make_float4(0.f, 0.f, 0.f, 0.f);
        if (gy >= 0 && gy < HH && gx >= 0 && gx < WW)
            v = *reinterpret_cast<const float4*>(
                V + ((size_t)(b * HH + gy) * WW + gx) * CC + c4 * 4);
        *reinterpret_cast<float4*>(sv + r * SV_STRIDE + c4 * 4) = v;
    }
    __syncthreads();

    // ---- Phase 2: scores (4 threads per pixel, ~13 neighbors each) ----
    const int p   = t >> 2;       // pixel 0..63
    const int sub = t & 3;        // 0..3
    const int pry = p >> 3, prx = p & 7;

    for (int n = sub; n < 49; n += 4) {
        int dy = n / 7, dx = n % 7;          // 0..6
        int gy = ty0 + pry + dy - PADW;
        int gx = tx0 + prx + dx - PADW;
        float sc;
        if (gy >= 0 && gy < HH && gx >= 0 && gx < WW) {
            const float* qr = sq + p * SQ_STRIDE;
            const float* kr = sk + ((pry + dy) * WIN + prx + dx) * SK_STRIDE;
            float acc = 0.0f;
#pragma unroll
            for (int c = 0; c < KD; c++) acc = fmaf(qr[c], kr[c], acc);
            sc = acc * 0.125f;               // / sqrt(64)
        } else {
            sc = -1e30f;                     // padding mask
        }
        sw[p * SW_STRIDE + n] = sc;
    }
    __syncthreads();

    // ---- Phase 3: softmax per pixel (threads 0..63) ----
    if (t < 64) {
        float* r = sw + t * SW_STRIDE;
        float m = r[0];
#pragma unroll
        for (int n = 1; n < 49; n++) m = fmaxf(m, r[n]);
        float sum = 0.0f;
#pragma unroll
        for (int n = 0; n < 49; n++) { float e = __expf(r[n] - m); r[n] = e; sum += e; }
        float inv = 1.0f / sum;
#pragma unroll
        for (int n = 0; n < 49; n++) r[n] *= inv;
    }
    __syncthreads();

    // ---- Phase 4: weighted V sum. Thread = (pixel p, channel chunk sub*32) ----
    float acc[32];
#pragma unroll
    for (int c = 0; c < 32; c++) acc[c] = 0.0f;

    const float* wr = sw + p * SW_STRIDE;
    const int chbase = sub * 32;
    for (int n = 0; n < 49; n++) {
        int dy = n / 7, dx = n % 7;
        const float* vr = sv + ((pry + dy) * WIN + prx + dx) * SV_STRIDE + chbase;
        float wgt = wr[n];
#pragma unroll
        for (int c4 = 0; c4 < 8; c4++) {
            float4 v = *reinterpret_cast<const float4*>(vr + c4 * 4);
            acc[c4 * 4 + 0] = fmaf(wgt, v.x, acc[c4 * 4 + 0]);
            acc[c4 * 4 + 1] = fmaf(wgt, v.y, acc[c4 * 4 + 1]);
            acc[c4 * 4 + 2] = fmaf(wgt, v.z, acc[c4 * 4 + 2]);
            acc[c4 * 4 + 3] = fmaf(wgt, v.w, acc[c4 * 4 + 3]);
        }
    }

    {
        int py = ty0 + pry, px = tx0 + prx;
        float* o = out + ((size_t)(b * HH + py) * WW + px) * CC + chbase;
#pragma unroll
        for (int c4 = 0; c4 < 8; c4++) {
            float4 v;
            v.x = acc[c4 * 4 + 0]; v.y = acc[c4 * 4 + 1];
            v.z = acc[c4 * 4 + 2]; v.w = acc[c4 * 4 + 3];
            *reinterpret_cast<float4*>(o + c4 * 4) = v;
        }
    }
}

// ---------------------------------------------------------------------------
extern "C" void kernel_launch(void* const* d_in, const int* in_sizes, int n_in,
                              void* d_out, int out_size)
{
    const float* Q  = (const float*)d_in[0];
    const float* K  = (const float*)d_in[1];
    const float* V  = (const float*)d_in[2];
    const float* Wq = (const float*)d_in[3];
    const float* bq = (const float*)d_in[4];
    const float* Wk = (const float*)d_in[5];
    const float* bk = (const float*)d_in[6];
    const float* Wv = (const float*)d_in[7];
    const float* bv = (const float*)d_in[8];
    float* out = (float*)d_out;

    float *qp, *kp, *ap;
    cudaGetSymbolAddress((void**)&qp, g_q);
    cudaGetSymbolAddress((void**)&kp, g_k);
    cudaGetSymbolAddress((void**)&ap, g_attn);

    const int smem_g64  = (64 * 129 + 128 * 64) * 4;    // 65792 B
    const int smem_g128 = (64 * 129 + 128 * 128) * 4;   // 98560 B
    const int smem_attn = SMEM_ATTN_FLOATS * 4;         // 184400 B

    cudaFuncSetAttribute((const void*)gemm128_kernel<64, false>,
                         cudaFuncAttributeMaxDynamicSharedMemorySize, smem_g64);
    cudaFuncSetAttribute((const void*)gemm128_kernel<128, true>,
                         cudaFuncAttributeMaxDynamicSharedMemorySize, smem_g128);
    cudaFuncSetAttribute((const void*)attn_kernel,
                         cudaFuncAttributeMaxDynamicSharedMemorySize, smem_attn);

    const int gemm_blocks = NPIX / 64;  // 288

    // q = Q@Wq + bq ; k = K@Wk + bk
    gemm128_kernel<64, false><<<gemm_blocks, 256, smem_g64>>>(Q, Wq, bq, qp);
    gemm128_kernel<64, false><<<gemm_blocks, 256, smem_g64>>>(K, Wk, bk, kp);

    // windowed attention -> g_attn
    dim3 agrid(WW / TS, HH / TS, BATCH);  // (12,12,2)
    attn_kernel<<<agrid, 256, smem_attn>>>(qp, kp, V, ap);

    // out = relu(g_attn @ Wv + bv)
    gemm128_kernel<128, true><<<gemm_blocks, 256, smem_g128>>>(ap, Wv, bv, out);
}

// round 2
// speedup vs baseline: 1.0543x; 1.0543x over previous
#include <cuda_runtime.h>
#include <cuda_bf16.h>
#include <cstdint>

// Problem constants
#define BATCH 2
#define HH 96
#define WW 96
#define CC 128
#define KD 64
#define OD 128
#define KS 7
#define PADW 3
#define NPIX (BATCH * HH * WW)   // 18432

// Scratch (allocation-free rule: __device__ globals)
__device__ float g_q[NPIX * KD];
__device__ float g_k[NPIX * KD];
__device__ float g_attn[NPIX * OD];

// ---------------------------------------------------------------------------
// Tiled GEMM v2: C[M,N] = A[M,128] @ W[128,N] + bias, optional relu.
// BM=128 rows/block, 256 threads, full K=128 staged in smem.
// Thread grid 16x16: ty=t>>4 owns rows ty*8..+7, tx=t&15 owns cols tx*TN..+TN-1.
// Per k-step: 8 broadcast scalar LDS (a) + TN/4 LDS.128 (w) feeding 8*TN FMA.
// ---------------------------------------------------------------------------
#define AS_STRIDE 129   // 8*129 % 32 == 8 -> ty groups hit different banks

template <int N, bool RELU>
__global__ __launch_bounds__(256) void gemm128_kernel(
    const float* __restrict__ A,
    const float* __restrict__ Wt,
    const float* __restrict__ bias,
    float* __restrict__ C)
{
    extern __shared__ float sm[];
    float* As = sm;                   // [128][129]
    float* Ws = As + 128 * AS_STRIDE; // [128][N]

    const int m0 = blockIdx.x * 128;
    const int t  = threadIdx.x;

    // Load A tile: 128 rows x 128 cols = 4096 float4-equiv, coalesced reads
    for (int i = t; i < 4096; i += 256) {
        int r  = i >> 5;   // row
        int c4 = i & 31;   // float4 index within row
        float4 v = *reinterpret_cast<const float4*>(A + (size_t)(m0 + r) * 128 + c4 * 4);
        float* d = As + r * AS_STRIDE + c4 * 4;
        d[0] = v.x; d[1] = v.y; d[2] = v.z; d[3] = v.w;
    }
    // Load W: 128 x N floats
    for (int i = t; i < 128 * N / 4; i += 256) {
        *reinterpret_cast<float4*>(Ws + i * 4) =
            *reinterpret_cast<const float4*>(Wt + i * 4);
    }
    __syncthreads();

    constexpr int TN = N / 16;        // 4 (N=64) or 8 (N=128)
    const int ty = t >> 4;            // 0..15 -> rows ty*8..+7
    const int tx = t & 15;            // 0..15 -> cols tx*TN..+TN-1

    float acc[8][TN];
#pragma unroll
    for (int i = 0; i < 8; i++)
#pragma unroll
        for (int j = 0; j < TN; j++) acc[i][j] = 0.0f;

#pragma unroll 4
    for (int kk = 0; kk < 128; kk++) {
        float a[8];
#pragma unroll
        for (int i = 0; i < 8; i++) a[i] = As[(ty * 8 + i) * AS_STRIDE + kk];
        float w[TN];
#pragma unroll
        for (int j4 = 0; j4 < TN / 4; j4++) {
            float4 wv = *reinterpret_cast<const float4*>(Ws + kk * N + tx * TN + j4 * 4);
            w[j4 * 4 + 0] = wv.x; w[j4 * 4 + 1] = wv.y;
            w[j4 * 4 + 2] = wv.z; w[j4 * 4 + 3] = wv.w;
        }
#pragma unroll
        for (int i = 0; i < 8; i++)
#pragma unroll
            for (int j = 0; j < TN; j++)
                acc[i][j] = fmaf(a[i], w[j], acc[i][j]);
    }

    // Epilogue
#pragma unroll
    for (int i = 0; i < 8; i++) {
        int row = m0 + ty * 8 + i;
#pragma unroll
        for (int j4 = 0; j4 < TN / 4; j4++) {
            int cb = tx * TN + j4 * 4;
            float4 o;
            o.x = acc[i][j4 * 4 + 0] + bias[cb + 0];
            o.y = acc[i][j4 * 4 + 1] + bias[cb + 1];
            o.z = acc[i][j4 * 4 + 2] + bias[cb + 2];
            o.w = acc[i][j4 * 4 + 3] + bias[cb + 3];
            if (RELU) {
                o.x = fmaxf(o.x, 0.0f); o.y = fmaxf(o.y, 0.0f);
                o.z = fmaxf(o.z, 0.0f); o.w = fmaxf(o.w, 0.0f);
            }
            *reinterpret_cast<float4*>(C + (size_t)row * N + cb) = o;
        }
    }
}

// Fused q/k projection: blockIdx.y selects (Q,Wq,bq->g_q) or (K,Wk,bk->g_k).
__global__ __launch_bounds__(256) void gemm_qk_kernel(
    const float* __restrict__ Q,  const float* __restrict__ K,
    const float* __restrict__ Wq, const float* __restrict__ Wk,
    const float* __restrict__ bq, const float* __restrict__ bk,
    float* __restrict__ qout,     float* __restrict__ kout)
{
    extern __shared__ float sm[];
    float* As = sm;                   // [128][129]
    float* Ws = As + 128 * AS_STRIDE; // [128][64]

    const bool isK = (blockIdx.y != 0);
    const float* A    = isK ? K  : Q;
    const float* Wt   = isK ? Wk : Wq;
    const float* bias = isK ? bk : bq;
    float*       C    = isK ? kout : qout;

    const int m0 = blockIdx.x * 128;
    const int t  = threadIdx.x;

    for (int i = t; i < 4096; i += 256) {
        int r  = i >> 5;
        int c4 = i & 31;
        float4 v = *reinterpret_cast<const float4*>(A + (size_t)(m0 + r) * 128 + c4 * 4);
        float* d = As + r * AS_STRIDE + c4 * 4;
        d[0] = v.x; d[1] = v.y; d[2] = v.z; d[3] = v.w;
    }
    for (int i = t; i < 128 * 64 / 4; i += 256) {
        *reinterpret_cast<float4*>(Ws + i * 4) =
            *reinterpret_cast<const float4*>(Wt + i * 4);
    }
    __syncthreads();

    const int ty = t >> 4;
    const int tx = t & 15;

    float acc[8][4];
#pragma unroll
    for (int i = 0; i < 8; i++)
#pragma unroll
        for (int j = 0; j < 4; j++) acc[i][j] = 0.0f;

#pragma unroll 4
    for (int kk = 0; kk < 128; kk++) {
        float a[8];
#pragma unroll
        for (int i = 0; i < 8; i++) a[i] = As[(ty * 8 + i) * AS_STRIDE + kk];
        float4 wv = *reinterpret_cast<const float4*>(Ws + kk * 64 + tx * 4);
#pragma unroll
        for (int i = 0; i < 8; i++) {
            acc[i][0] = fmaf(a[i], wv.x, acc[i][0]);
            acc[i][1] = fmaf(a[i], wv.y, acc[i][1]);
            acc[i][2] = fmaf(a[i], wv.z, acc[i][2]);
            acc[i][3] = fmaf(a[i], wv.w, acc[i][3]);
        }
    }

#pragma unroll
    for (int i = 0; i < 8; i++) {
        int row = m0 + ty * 8 + i;
        float4 o;
        o.x = acc[i][0] + bias[tx * 4 + 0];
        o.y = acc[i][1] + bias[tx * 4 + 1];
        o.z = acc[i][2] + bias[tx * 4 + 2];
        o.w = acc[i][3] + bias[tx * 4 + 3];
        *reinterpret_cast<float4*>(C + (size_t)row * 64 + tx * 4) = o;
    }
}

// ---------------------------------------------------------------------------
// Neighborhood attention: 8x8 pixel tile per block, 512 threads.
// Strides multiple-of-4 so all hot smem accesses are LDS.128.
// ---------------------------------------------------------------------------
#define TS 8
#define WIN 14                // TS + KS - 1
#define SQ_STRIDE 68
#define SK_STRIDE 68
#define SV_STRIDE 132
#define SW_STRIDE 52

#define SMEM_ATTN_FLOATS (64 * SQ_STRIDE + 196 * SK_STRIDE + 196 * SV_STRIDE + 64 * SW_STRIDE)

__global__ __launch_bounds__(512) void attn_kernel(
    const float* __restrict__ qbuf,
    const float* __restrict__ kbuf,
    const float* __restrict__ V,
    float* __restrict__ out)
{
    extern __shared__ float sm[];
    float* sq = sm;                         // [64][68]
    float* sk = sq + 64 * SQ_STRIDE;        // [196][68]
    float* sv = sk + 196 * SK_STRIDE;       // [196][132]
    float* sw = sv + 196 * SV_STRIDE;       // [64][52]

    const int b   = blockIdx.z;
    const int ty0 = blockIdx.y * TS;
    const int tx0 = blockIdx.x * TS;
    const int t   = threadIdx.x;

    // ---- Phase 1: cooperative loads ----
    for (int i = t; i < 64 * 16; i += 512) {
        int p = i >> 4, c4 = i & 15;
        int py = ty0 + (p >> 3), px = tx0 + (p & 7);
        float4 v = *reinterpret_cast<const float4*>(
            qbuf + ((size_t)(b * HH + py) * WW + px) * KD + c4 * 4);
        *reinterpret_cast<float4*>(sq + p * SQ_STRIDE + c4 * 4) = v;
    }
    for (int i = t; i < 196 * 16; i += 512) {
        int r = i >> 4, c4 = i & 15;
        int gy = ty0 - PADW + r / WIN;
        int gx = tx0 - PADW + r % WIN;
        float4 v = make_float4(0.f, 0.f, 0.f, 0.f);
        if (gy >= 0 && gy < HH && gx >= 0 && gx < WW)
            v = *reinterpret_cast<const float4*>(
                kbuf + ((size_t)(b * HH + gy) * WW + gx) * KD + c4 * 4);
        *reinterpret_cast<float4*>(sk + r * SK_STRIDE + c4 * 4) = v;
    }
    for (int i = t; i < 196 * 32; i += 512) {
        int r = i >> 5, c4 = i & 31;
        int gy = ty0 - PADW + r / WIN;
        int gx = tx0 - PADW + r % WIN;
        float4 v = make_float4(0.f, 0.f, 0.f, 0.f);
        if (gy >= 0 && gy < HH && gx >= 0 && gx < WW)
            v = *reinterpret_cast<const float4*>(
                V + ((size_t)(b * HH + gy) * WW + gx) * CC + c4 * 4);
        *reinterpret_cast<float4*>(sv + r * SV_STRIDE + c4 * 4) = v;
    }
    __syncthreads();

    // ---- Phase 2: scores (8 threads per pixel over 49 neighbors) ----
    const int p   = t >> 3;       // pixel 0..63
    const int sub = t & 7;        // 0..7
    const int pry = p >> 3, prx = p & 7;

    const float4* q4 = reinterpret_cast<const float4*>(sq + p * SQ_STRIDE);
    for (int n = sub; n < 49; n += 8) {
        int dy = n / 7, dx = n % 7;
        int gy = ty0 + pry + dy - PADW;
        int gx = tx0 + prx + dx - PADW;
        float sc;
        if (gy >= 0 && gy < HH && gx >= 0 && gx < WW) {
            const float4* k4 = reinterpret_cast<const float4*>(
                sk + ((pry + dy) * WIN + prx + dx) * SK_STRIDE);
            float acc = 0.0f;
#pragma unroll
            for (int c4 = 0; c4 < 16; c4++) {
                float4 qv = q4[c4], kv = k4[c4];
                acc = fmaf(qv.x, kv.x, acc);
                acc = fmaf(qv.y, kv.y, acc);
                acc = fmaf(qv.z, kv.z, acc);
                acc = fmaf(qv.w, kv.w, acc);
            }
            sc = acc * 0.125f;               // 1/sqrt(64)
        } else {
            sc = -1e30f;
        }
        sw[p * SW_STRIDE + n] = sc;
    }
    __syncthreads();

    // ---- Phase 3: softmax per pixel ----
    if (t < 64) {
        float* r = sw + t * SW_STRIDE;
        float m = r[0];
#pragma unroll
        for (int n = 1; n < 49; n++) m = fmaxf(m, r[n]);
        float sum = 0.0f;
#pragma unroll
        for (int n = 0; n < 49; n++) { float e = __expf(r[n] - m); r[n] = e; sum += e; }
        float inv = 1.0f / sum;
#pragma unroll
        for (int n = 0; n < 49; n++) r[n] *= inv;
    }
    __syncthreads();

    // ---- Phase 4: weighted V sum. Thread = (pixel p, 16 channels at sub*16) ----
    float acc[16];
#pragma unroll
    for (int c = 0; c < 16; c++) acc[c] = 0.0f;

    const float* wr = sw + p * SW_STRIDE;
    const int chbase = sub * 16;
#pragma unroll 7
    for (int n = 0; n < 49; n++) {
        int dy = n / 7, dx = n % 7;
        const float* vr = sv + ((pry + dy) * WIN + prx + dx) * SV_STRIDE + chbase;
        float wgt = wr[n];
#pragma unroll
        for (int c4 = 0; c4 < 4; c4++) {
            float4 v = *reinterpret_cast<const float4*>(vr + c4 * 4);
            acc[c4 * 4 + 0] = fmaf(wgt, v.x, acc[c4 * 4 + 0]);
            acc[c4 * 4 + 1] = fmaf(wgt, v.y, acc[c4 * 4 + 1]);
            acc[c4 * 4 + 2] = fmaf(wgt, v.z, acc[c4 * 4 + 2]);
            acc[c4 * 4 + 3] = fmaf(wgt, v.w, acc[c4 * 4 + 3]);
        }
    }

    {
        int py = ty0 + pry, px = tx0 + prx;
        float* o = out + ((size_t)(b * HH + py) * WW + px) * CC + chbase;
#pragma unroll
        for (int c4 = 0; c4 < 4; c4++) {
            float4 v;
            v.x = acc[c4 * 4 + 0]; v.y = acc[c4 * 4 + 1];
            v.z = acc[c4 * 4 + 2]; v.w = acc[c4 * 4 + 3];
            *reinterpret_cast<float4*>(o + c4 * 4) = v;
        }
    }
}

// ---------------------------------------------------------------------------
extern "C" void kernel_launch(void* const* d_in, const int* in_sizes, int n_in,
                              void* d_out, int out_size)
{
    const float* Q  = (const float*)d_in[0];
    const float* K  = (const float*)d_in[1];
    const float* V  = (const float*)d_in[2];
    const float* Wq = (const float*)d_in[3];
    const float* bq = (const float*)d_in[4];
    const float* Wk = (const float*)d_in[5];
    const float* bk = (const float*)d_in[6];
    const float* Wv = (const float*)d_in[7];
    const float* bv = (const float*)d_in[8];
    float* out = (float*)d_out;

    float *qp, *kp, *ap;
    cudaGetSymbolAddress((void**)&qp, g_q);
    cudaGetSymbolAddress((void**)&kp, g_k);
    cudaGetSymbolAddress((void**)&ap, g_attn);

    const int smem_g64  = (128 * AS_STRIDE + 128 * 64) * 4;    // 98,816 B
    const int smem_g128 = (128 * AS_STRIDE + 128 * 128) * 4;   // 131,584 B
    const int smem_attn = SMEM_ATTN_FLOATS * 4;                // 187,520 B

    cudaFuncSetAttribute((const void*)gemm_qk_kernel,
                         cudaFuncAttributeMaxDynamicSharedMemorySize, smem_g64);
    cudaFuncSetAttribute((const void*)gemm128_kernel<128, true>,
                         cudaFuncAttributeMaxDynamicSharedMemorySize, smem_g128);
    cudaFuncSetAttribute((const void*)attn_kernel,
                         cudaFuncAttributeMaxDynamicSharedMemorySize, smem_attn);

    const int gemm_blocks = NPIX / 128;  // 144

    // q = Q@Wq + bq and k = K@Wk + bk, fused into one launch (grid 144x2)
    gemm_qk_kernel<<<dim3(gemm_blocks, 2), 256, smem_g64>>>(Q, K, Wq, Wk, bq, bk, qp, kp);

    // windowed attention -> g_attn
    dim3 agrid(WW / TS, HH / TS, BATCH);  // (12,12,2)
    attn_kernel<<<agrid, 512, smem_attn>>>(qp, kp, V, ap);

    // out = relu(g_attn @ Wv + bv)
    gemm128_kernel<128, true><<<gemm_blocks, 256, smem_g128>>>(ap, Wv, bv, out);
}

// round 3
// speedup vs baseline: 1.5400x; 1.4607x over previous
#include <cuda_runtime.h>
#include <cstdint>

typedef unsigned long long u64;

// Problem constants
#define BATCH 2
#define HH 96
#define WW 96
#define CC 128
#define KD 64
#define OD 128
#define NPIX (BATCH * HH * WW)   // 18432

// Scratch (allocation-free rule: __device__ globals)
__device__ float g_q[NPIX * KD];
__device__ float g_k[NPIX * KD];
__device__ float g_attn[NPIX * OD];

// ---- packed f32x2 helpers (FFMA2: PTX-only on sm_103a) ----
__device__ __forceinline__ u64 pack2(float lo, float hi) {
    u64 r; asm("mov.b64 %0, {%1, %2};" : "=l"(r) : "f"(lo), "f"(hi)); return r;
}
__device__ __forceinline__ u64 dup2(float v) { return pack2(v, v); }
__device__ __forceinline__ void fma2(u64& d, u64 a, u64 b) {
    asm("fma.rn.f32x2 %0, %1, %2, %0;" : "+l"(d) : "l"(a), "l"(b));
}
__device__ __forceinline__ float2 unpack2(u64 v) {
    float2 f; asm("mov.b64 {%0, %1}, %2;" : "=f"(f.x), "=f"(f.y) : "l"(v)); return f;
}

// ---------------------------------------------------------------------------
// GEMM: C[M,N] = A[M,128] @ W[128,N] + bias (+relu).  256 threads.
// BM = 16384/N (256 for N=64, 128 for N=128). 8x8 per-thread tile, f32x2 acc.
// ---------------------------------------------------------------------------
#define AS_PAD 129

template <int N, bool RELU>
__device__ __forceinline__ void gemm_body(const float* __restrict__ A,
                                          const float* __restrict__ W,
                                          const float* __restrict__ bias,
                                          float* __restrict__ C, int m0)
{
    constexpr int BM  = 16384 / N;   // 256 or 128
    constexpr int NTX = N / 8;       // 8 or 16
    extern __shared__ float sm[];
    float* As = sm;                  // [BM][129]
    float* Ws = As + BM * AS_PAD;    // [128][N]

    const int t = threadIdx.x;

    // Stage A tile (coalesced float4)
    for (int i = t; i < BM * 32; i += 256) {
        int r = i >> 5, c4 = i & 31;
        float4 v = *reinterpret_cast<const float4*>(A + (size_t)(m0 + r) * 128 + c4 * 4);
        float* d = As + r * AS_PAD + c4 * 4;
        d[0] = v.x; d[1] = v.y; d[2] = v.z; d[3] = v.w;
    }
    // Stage W (128 x N)
    for (int i = t; i < 32 * N; i += 256) {
        *reinterpret_cast<float4*>(Ws + i * 4) =
            *reinterpret_cast<const float4*>(W + i * 4);
    }
    __syncthreads();

    const int ty = t / NTX;
    const int tx = t % NTX;
    const int row0 = ty * 8;
    const int col0 = tx * 8;

    u64 acc[8][4];
#pragma unroll
    for (int i = 0; i < 8; i++)
#pragma unroll
        for (int j = 0; j < 4; j++) acc[i][j] = 0ull;

#pragma unroll 4
    for (int kk = 0; kk < 128; kk++) {
        const float* arow = As + row0 * AS_PAD + kk;
        u64 a2[8];
#pragma unroll
        for (int i = 0; i < 8; i++) a2[i] = dup2(arow[i * AS_PAD]);

        const float* wrow = Ws + kk * N + col0;
        float4 w0 = *reinterpret_cast<const float4*>(wrow);
        float4 w1 = *reinterpret_cast<const float4*>(wrow + 4);
        u64 w2[4] = { pack2(w0.x, w0.y), pack2(w0.z, w0.w),
                      pack2(w1.x, w1.y), pack2(w1.z, w1.w) };
#pragma unroll
        for (int i = 0; i < 8; i++)
#pragma unroll
            for (int j = 0; j < 4; j++)
                fma2(acc[i][j], a2[i], w2[j]);
    }

    // Epilogue
    float bv[8];
#pragma unroll
    for (int j = 0; j < 8; j++) bv[j] = bias[col0 + j];

#pragma unroll
    for (int i = 0; i < 8; i++) {
        float o[8];
#pragma unroll
        for (int j = 0; j < 4; j++) {
            float2 f = unpack2(acc[i][j]);
            o[j * 2 + 0] = f.x + bv[j * 2 + 0];
            o[j * 2 + 1] = f.y + bv[j * 2 + 1];
        }
        if (RELU) {
#pragma unroll
            for (int j = 0; j < 8; j++) o[j] = fmaxf(o[j], 0.0f);
        }
        float* cp = C + (size_t)(m0 + row0 + i) * N + col0;
        *reinterpret_cast<float4*>(cp)     = make_float4(o[0], o[1], o[2], o[3]);
        *reinterpret_cast<float4*>(cp + 4) = make_float4(o[4], o[5], o[6], o[7]);
    }
}

// q/k projections fused: blockIdx.y selects operand set. N=64, BM=256.
__global__ __launch_bounds__(256) void gemm_qk_kernel(
    const float* __restrict__ Q,  const float* __restrict__ K,
    const float* __restrict__ Wq, const float* __restrict__ Wk,
    const float* __restrict__ bq, const float* __restrict__ bk,
    float* __restrict__ qout,     float* __restrict__ kout)
{
    const bool isK = (blockIdx.y != 0);
    gemm_body<64, false>(isK ? K : Q, isK ? Wk : Wq, isK ? bk : bq,
                         isK ? kout : qout, blockIdx.x * 256);
}

// Output projection: N=128, BM=128, relu.
__global__ __launch_bounds__(256) void gemm_out_kernel(
    const float* __restrict__ A, const float* __restrict__ W,
    const float* __restrict__ bias, float* __restrict__ C)
{
    gemm_body<128, true>(A, W, bias, C, blockIdx.x * 128);
}

// ---------------------------------------------------------------------------
// Neighborhood attention: 8x8 pixel tile / block, 256 threads.
// smem: sq[64][68], sk[196][68], sv[196][132], sw[64][52], sw2[98][64]
// ---------------------------------------------------------------------------
#define TS 8
#define WIN 14
#define SQS 68
#define SKS 68
#define SVS 132
#define SWS 52
#define SMEM_ATTN_FLOATS (64*SQS + 196*SKS + 196*SVS + 64*SWS + 98*64)

__global__ __launch_bounds__(256) void attn_kernel(
    const float* __restrict__ qbuf,
    const float* __restrict__ kbuf,
    const float* __restrict__ V,
    float* __restrict__ out)
{
    extern __shared__ float sm[];
    float* sq  = sm;                  // [64][68]
    float* sk  = sq + 64 * SQS;       // [196][68]
    float* sv  = sk + 196 * SKS;      // [196][132]
    float* sw  = sv + 196 * SVS;      // [64][52]
    float* sw2 = sw + 64 * SWS;       // [98][64]  transposed padded weights

    const int b   = blockIdx.z;
    const int ty0 = blockIdx.y * TS;
    const int tx0 = blockIdx.x * TS;
    const int t   = threadIdx.x;

    // ---- Phase 1a: async V halo load (overlaps with phase 2) ----
    for (int i = t; i < 196 * 32; i += 256) {
        int r = i >> 5, c4 = i & 31;
        int gy = ty0 - 3 + r / WIN;
        int gx = tx0 - 3 + r % WIN;
        bool ok = (gy >= 0 && gy < HH && gx >= 0 && gx < WW);
        const float* src = V + ((size_t)(b * HH + (ok ? gy : 0)) * WW + (ok ? gx : 0)) * CC + c4 * 4;
        uint32_t daddr = (uint32_t)__cvta_generic_to_shared(sv + r * SVS + c4 * 4);
        int sz = ok ? 16 : 0;
        asm volatile("cp.async.cg.shared.global [%0], [%1], 16, %2;"
                     :: "r"(daddr), "l"(src), "r"(sz));
    }
    asm volatile("cp.async.commit_group;");

    // ---- Phase 1b: zero sw2, load sq, sk ----
    for (int i = t; i < 98 * 64; i += 256) sw2[i] = 0.0f;

    for (int i = t; i < 64 * 16; i += 256) {
        int p = i >> 4, c4 = i & 15;
        int py = ty0 + (p >> 3), px = tx0 + (p & 7);
        float4 v = *reinterpret_cast<const float4*>(
            qbuf + ((size_t)(b * HH + py) * WW + px) * KD + c4 * 4);
        *reinterpret_cast<float4*>(sq + p * SQS + c4 * 4) = v;
    }
    for (int i = t; i < 196 * 16; i += 256) {
        int r = i >> 4, c4 = i & 15;
        int gy = ty0 - 3 + r / WIN;
        int gx = tx0 - 3 + r % WIN;
        float4 v = make_float4(0.f, 0.f, 0.f, 0.f);
        if (gy >= 0 && gy < HH && gx >= 0 && gx < WW)
            v = *reinterpret_cast<const float4*>(
                kbuf + ((size_t)(b * HH + gy) * WW + gx) * KD + c4 * 4);
        *reinterpret_cast<float4*>(sk + r * SKS + c4 * 4) = v;
    }
    __syncthreads();

    // ---- Phase 2: scores. thread = (pixel p, sub 0..3 -> 16 channels) ----
    const int p   = t >> 2;
    const int sub = t & 3;
    const int pry = p >> 3, prx = p & 7;

    u64 q2[8];
    {
        const float* qr = sq + p * SQS + sub * 16;
#pragma unroll
        for (int j4 = 0; j4 < 4; j4++) {
            float4 qv = *reinterpret_cast<const float4*>(qr + j4 * 4);
            q2[j4 * 2 + 0] = pack2(qv.x, qv.y);
            q2[j4 * 2 + 1] = pack2(qv.z, qv.w);
        }
    }

    for (int dy = 0; dy < 7; dy++) {
        const int hy = pry + dy;
        const int gy = ty0 + hy - 3;
#pragma unroll
        for (int dx = 0; dx < 7; dx++) {
            const int hx = prx + dx;
            const int gx = tx0 + hx - 3;
            const float* kr = sk + (hy * WIN + hx) * SKS + sub * 16;
            u64 acc0 = 0ull, acc1 = 0ull;
#pragma unroll
            for (int j4 = 0; j4 < 4; j4++) {
                float4 kv = *reinterpret_cast<const float4*>(kr + j4 * 4);
                fma2(acc0, q2[j4 * 2 + 0], pack2(kv.x, kv.y));
                fma2(acc1, q2[j4 * 2 + 1], pack2(kv.z, kv.w));
            }
            float2 s0 = unpack2(acc0), s1 = unpack2(acc1);
            float part = (s0.x + s0.y) + (s1.x + s1.y);
            part += __shfl_xor_sync(0xffffffffu, part, 1);
            part += __shfl_xor_sync(0xffffffffu, part, 2);
            if (sub == 0) {
                bool valid = (gy >= 0 && gy < HH && gx >= 0 && gx < WW);
                sw[p * SWS + dy * 7 + dx] = valid ? part * 0.125f : -1e30f;
            }
        }
    }
    __syncthreads();

    // ---- Phase 3: softmax per pixel; scatter into transposed table sw2 ----
    if (t < 64) {
        const int pp  = t;
        const int ppx = t & 7;
        float* r = sw + pp * SWS;
        float m = r[0];
#pragma unroll
        for (int n = 1; n < 49; n++) m = fmaxf(m, r[n]);
        float e[49]; float sum = 0.0f;
#pragma unroll
        for (int n = 0; n < 49; n++) { e[n] = __expf(r[n] - m); sum += e[n]; }
        float inv = 1.0f / sum;
#pragma unroll
        for (int n = 0; n < 49; n++) {
            int dy = n / 7, dx = n % 7;
            sw2[(dy * 14 + ppx + dx) * 64 + pp] = e[n] * inv;
        }
    }
    asm volatile("cp.async.wait_group 0;");
    __syncthreads();

    // ---- Phase 4: out = weights @ V halo. thread = (pixel row, 4-ch chunk) ----
    // 8 pixels x 4 channels per thread; each V float4 feeds 16 FMA2.
    const int row = t >> 5;   // 0..7
    const int cc  = t & 31;   // channel chunk

    u64 acc[8][2];
#pragma unroll
    for (int j = 0; j < 8; j++) { acc[j][0] = 0ull; acc[j][1] = 0ull; }

    for (int dy = 0; dy < 7; dy++) {
        const float* svrow = sv + (row + dy) * WIN * SVS + cc * 4;
        const float* wrow  = sw2 + (dy * 14) * 64 + row * 8;
#pragma unroll
        for (int wx = 0; wx < 14; wx++) {
            float4 v = *reinterpret_cast<const float4*>(svrow + wx * SVS);
            u64 v0 = pack2(v.x, v.y), v1 = pack2(v.z, v.w);
            const float* wp = wrow + wx * 64;
            float4 wa = *reinterpret_cast<const float4*>(wp);
            float4 wb = *reinterpret_cast<const float4*>(wp + 4);
            u64 wj;
            wj = dup2(wa.x); fma2(acc[0][0], wj, v0); fma2(acc[0][1], wj, v1);
            wj = dup2(wa.y); fma2(acc[1][0], wj, v0); fma2(acc[1][1], wj, v1);
            wj = dup2(wa.z); fma2(acc[2][0], wj, v0); fma2(acc[2][1], wj, v1);
            wj = dup2(wa.w); fma2(acc[3][0], wj, v0); fma2(acc[3][1], wj, v1);
            wj = dup2(wb.x); fma2(acc[4][0], wj, v0); fma2(acc[4][1], wj, v1);
            wj = dup2(wb.y); fma2(acc[5][0], wj, v0); fma2(acc[5][1], wj, v1);
            wj = dup2(wb.z); fma2(acc[6][0], wj, v0); fma2(acc[6][1], wj, v1);
            wj = dup2(wb.w); fma2(acc[7][0], wj, v0); fma2(acc[7][1], wj, v1);
        }
    }

    {
        const int py = ty0 + row;
#pragma unroll
        for (int j = 0; j < 8; j++) {
            float2 lo = unpack2(acc[j][0]);
            float2 hi = unpack2(acc[j][1]);
            float* o = out + ((size_t)(b * HH + py) * WW + tx0 + j) * CC + cc * 4;
            *reinterpret_cast<float4*>(o) = make_float4(lo.x, lo.y, hi.x, hi.y);
        }
    }
}

// ---------------------------------------------------------------------------
extern "C" void kernel_launch(void* const* d_in, const int* in_sizes, int n_in,
                              void* d_out, int out_size)
{
    const float* Q  = (const float*)d_in[0];
    const float* K  = (const float*)d_in[1];
    const float* V  = (const float*)d_in[2];
    const float* Wq = (const float*)d_in[3];
    const float* bq = (const float*)d_in[4];
    const float* Wk = (const float*)d_in[5];
    const float* bk = (const float*)d_in[6];
    const float* Wv = (const float*)d_in[7];
    const float* bv = (const float*)d_in[8];
    float* out = (float*)d_out;

    float *qp, *kp, *ap;
    cudaGetSymbolAddress((void**)&qp, g_q);
    cudaGetSymbolAddress((void**)&kp, g_k);
    cudaGetSymbolAddress((void**)&ap, g_attn);

    const int smem_qk   = (256 * AS_PAD + 128 * 64) * 4;   // 164,864 B
    const int smem_out  = (128 * AS_PAD + 128 * 128) * 4;  // 131,584 B
    const int smem_attn = SMEM_ATTN_FLOATS * 4;            // 212,608 B

    cudaFuncSetAttribute((const void*)gemm_qk_kernel,
                         cudaFuncAttributeMaxDynamicSharedMemorySize, smem_qk);
    cudaFuncSetAttribute((const void*)gemm_out_kernel,
                         cudaFuncAttributeMaxDynamicSharedMemorySize, smem_out);
    cudaFuncSetAttribute((const void*)attn_kernel,
                         cudaFuncAttributeMaxDynamicSharedMemorySize, smem_attn);

    // q/k projections: one wave of 144 CTAs
    gemm_qk_kernel<<<dim3(NPIX / 256, 2), 256, smem_qk>>>(Q, K, Wq, Wk, bq, bk, qp, kp);

    // windowed attention
    dim3 agrid(WW / TS, HH / TS, BATCH);  // (12,12,2)
    attn_kernel<<<agrid, 256, smem_attn>>>(qp, kp, V, ap);

    // out = relu(attn @ Wv + bv): one wave of 144 CTAs
    gemm_out_kernel<<<NPIX / 128, 256, smem_out>>>(ap, Wv, bv, out);
}

// round 4
// speedup vs baseline: 1.5509x; 1.0071x over previous
#include <cuda_runtime.h>
#include <cstdint>

typedef unsigned long long u64;

// Problem constants
#define BATCH 2
#define HH 96
#define WW 96
#define CC 128
#define KD 64
#define OD 128
#define NPIX (BATCH * HH * WW)   // 18432

// Scratch (allocation-free rule)
__device__ float g_q[NPIX * KD];
__device__ float g_k[NPIX * KD];

// ---- packed f32x2 helpers ----
__device__ __forceinline__ u64 pack2(float lo, float hi) {
    u64 r; asm("mov.b64 %0, {%1, %2};" : "=l"(r) : "f"(lo), "f"(hi)); return r;
}
__device__ __forceinline__ u64 dup2(float v) { return pack2(v, v); }
__device__ __forceinline__ void fma2(u64& d, u64 a, u64 b) {
    asm("fma.rn.f32x2 %0, %1, %2, %0;" : "+l"(d) : "l"(a), "l"(b));
}
__device__ __forceinline__ float2 unpack2(u64 v) {
    float2 f; asm("mov.b64 {%0, %1}, %2;" : "=f"(f.x), "=f"(f.y) : "l"(v)); return f;
}
__device__ __forceinline__ float hsum2(u64 v) { float2 f = unpack2(v); return f.x + f.y; }
// 16B shared load directly into two u64 lane-pairs (no packing MOVs)
__device__ __forceinline__ void lds2(u64& a, u64& b, const float* p) {
    unsigned addr = (unsigned)__cvta_generic_to_shared(p);
    asm("ld.shared.v2.b64 {%0, %1}, [%2];" : "=l"(a), "=l"(b) : "r"(addr));
}
__device__ __forceinline__ void cpasync16(float* dst, const float* src, int sz) {
    unsigned daddr = (unsigned)__cvta_generic_to_shared(dst);
    asm volatile("cp.async.cg.shared.global [%0], [%1], 16, %2;"
                 :: "r"(daddr), "l"(src), "r"(sz));
}

// ---------------------------------------------------------------------------
// q/k projection GEMM: C[M,64] = A[M,128] @ W[128,64] + bias.
// BM=128, 256 threads, 8x4 tile, FFMA2 paired over k. 2 CTAs/SM.
// ---------------------------------------------------------------------------
#define ASP 132

__global__ __launch_bounds__(256, 2) void gemm_qk_kernel(
    const float* __restrict__ Q,  const float* __restrict__ K,
    const float* __restrict__ Wq, const float* __restrict__ Wk,
    const float* __restrict__ bq, const float* __restrict__ bk,
    float* __restrict__ qout,     float* __restrict__ kout)
{
    extern __shared__ float sm[];
    float* As = sm;                 // [128][132]
    float* Ws = As + 128 * ASP;     // [128][64]

    const bool isK = (blockIdx.y != 0);
    const float* A    = isK ? K  : Q;
    const float* W    = isK ? Wk : Wq;
    const float* bias = isK ? bk : bq;
    float*       C    = isK ? kout : qout;

    const int m0 = blockIdx.x * 128;
    const int t  = threadIdx.x;

    // Stage A (coalesced, conflict-free)
    for (int i = t; i < 4096; i += 256) {
        int r = i >> 5, c4 = i & 31;
        float4 v = *reinterpret_cast<const float4*>(A + (size_t)(m0 + r) * 128 + c4 * 4);
        *reinterpret_cast<float4*>(As + r * ASP + c4 * 4) = v;
    }
    // Stage W (128x64)
    for (int i = t; i < 2048; i += 256) {
        *reinterpret_cast<float4*>(Ws + i * 4) =
            *reinterpret_cast<const float4*>(W + i * 4);
    }
    __syncthreads();

    const int ty = t >> 4, tx = t & 15;
    const int row0 = ty * 8, col0 = tx * 4;

    u64 acc[8][4];
#pragma unroll
    for (int i = 0; i < 8; i++)
#pragma unroll
        for (int j = 0; j < 4; j++) acc[i][j] = 0ull;

#pragma unroll 2
    for (int kb = 0; kb < 32; kb++) {
        u64 a2[8][2];
#pragma unroll
        for (int i = 0; i < 8; i++)
            lds2(a2[i][0], a2[i][1], As + (row0 + i) * ASP + kb * 4);

        const float* wr = Ws + kb * 4 * 64 + col0;
        float4 w0 = *reinterpret_cast<const float4*>(wr);
        float4 w1 = *reinterpret_cast<const float4*>(wr + 64);
        float4 w2 = *reinterpret_cast<const float4*>(wr + 128);
        float4 w3 = *reinterpret_cast<const float4*>(wr + 192);
        u64 wp[4][2];
        wp[0][0] = pack2(w0.x, w1.x); wp[0][1] = pack2(w2.x, w3.x);
        wp[1][0] = pack2(w0.y, w1.y); wp[1][1] = pack2(w2.y, w3.y);
        wp[2][0] = pack2(w0.z, w1.z); wp[2][1] = pack2(w2.z, w3.z);
        wp[3][0] = pack2(w0.w, w1.w); wp[3][1] = pack2(w2.w, w3.w);

#pragma unroll
        for (int i = 0; i < 8; i++)
#pragma unroll
            for (int j = 0; j < 4; j++) {
                fma2(acc[i][j], a2[i][0], wp[j][0]);
                fma2(acc[i][j], a2[i][1], wp[j][1]);
            }
    }

    float b4[4];
#pragma unroll
    for (int j = 0; j < 4; j++) b4[j] = bias[col0 + j];

#pragma unroll
    for (int i = 0; i < 8; i++) {
        float4 o;
        o.x = hsum2(acc[i][0]) + b4[0];
        o.y = hsum2(acc[i][1]) + b4[1];
        o.z = hsum2(acc[i][2]) + b4[2];
        o.w = hsum2(acc[i][3]) + b4[3];
        *reinterpret_cast<float4*>(C + (size_t)(m0 + row0 + i) * 64 + col0) = o;
    }
}

// ---------------------------------------------------------------------------
// Fused neighborhood attention + output projection.
// 8x8 pixel tile / block, 512 threads.
// smem: sq[64][68] | sk[196][68] | sv[196][132] | sw[64][52] | sw2[98][64]
// Overlays: Wv[128][128] over sq+sk (after phase 2); at[64][132] over sv
// (after phase 4).
// ---------------------------------------------------------------------------
#define TS 8
#define WIN 14
#define SQS 68
#define SKS 68
#define SVS 132
#define SWS 52
#define ATS 132
#define SMEM_ATTN_FLOATS (64*SQS + 196*SKS + 196*SVS + 64*SWS + 98*64)  // 53152

__global__ __launch_bounds__(512, 1) void attn_fused_kernel(
    const float* __restrict__ qbuf,
    const float* __restrict__ kbuf,
    const float* __restrict__ V,
    const float* __restrict__ Wv,
    const float* __restrict__ bv,
    float* __restrict__ out)
{
    extern __shared__ float sm[];
    float* sq  = sm;                  // [64][68]
    float* sk  = sq + 64 * SQS;       // [196][68]
    float* sv  = sk + 196 * SKS;      // [196][132]
    float* sw  = sv + 196 * SVS;      // [64][52]
    float* sw2 = sw + 64 * SWS;       // [98][64]
    float* wvs = sm;                  // Wv overlay [128][128] over sq+sk
    float* at  = sv;                  // attn-out overlay [64][132] over sv

    const int b   = blockIdx.z;
    const int ty0 = blockIdx.y * TS;
    const int tx0 = blockIdx.x * TS;
    const int t   = threadIdx.x;

    // ---- Phase 1a: async V halo (group A) ----
    for (int i = t; i < 196 * 32; i += 512) {
        int r = i >> 5, c4 = i & 31;
        int gy = ty0 - 3 + r / WIN;
        int gx = tx0 - 3 + r % WIN;
        bool ok = (gy >= 0 && gy < HH && gx >= 0 && gx < WW);
        const float* src = V + ((size_t)(b * HH + (ok ? gy : 0)) * WW + (ok ? gx : 0)) * CC + c4 * 4;
        cpasync16(sv + r * SVS + c4 * 4, src, ok ? 16 : 0);
    }
    asm volatile("cp.async.commit_group;");

    // ---- Phase 1b: zero sw2, load sq, sk ----
    for (int i = t; i < 98 * 64; i += 512) sw2[i] = 0.0f;
    for (int i = t; i < 64 * 16; i += 512) {
        int p = i >> 4, c4 = i & 15;
        int py = ty0 + (p >> 3), px = tx0 + (p & 7);
        float4 v = *reinterpret_cast<const float4*>(
            qbuf + ((size_t)(b * HH + py) * WW + px) * KD + c4 * 4);
        *reinterpret_cast<float4*>(sq + p * SQS + c4 * 4) = v;
    }
    for (int i = t; i < 196 * 16; i += 512) {
        int r = i >> 4, c4 = i & 15;
        int gy = ty0 - 3 + r / WIN;
        int gx = tx0 - 3 + r % WIN;
        float4 v = make_float4(0.f, 0.f, 0.f, 0.f);
        if (gy >= 0 && gy < HH && gx >= 0 && gx < WW)
            v = *reinterpret_cast<const float4*>(
                kbuf + ((size_t)(b * HH + gy) * WW + gx) * KD + c4 * 4);
        *reinterpret_cast<float4*>(sk + r * SKS + c4 * 4) = v;
    }
    __syncthreads();

    // ---- Phase 2: scores. thread = (pixel p, sub 0..7 -> 8 channels) ----
    {
        const int p   = t >> 3;
        const int sub = t & 7;
        const int pry = p >> 3, prx = p & 7;

        u64 q2[4];
        lds2(q2[0], q2[1], sq + p * SQS + sub * 8);
        lds2(q2[2], q2[3], sq + p * SQS + sub * 8 + 4);

        for (int dy = 0; dy < 7; dy++) {
            const int hy = pry + dy;
            const int gy = ty0 + hy - 3;
#pragma unroll
            for (int dx = 0; dx < 7; dx++) {
                const int hx = prx + dx;
                const int gx = tx0 + hx - 3;
                const float* kr = sk + (hy * WIN + hx) * SKS + sub * 8;
                u64 k2a, k2b, k2c, k2d;
                lds2(k2a, k2b, kr);
                lds2(k2c, k2d, kr + 4);
                u64 acc0 = 0ull, acc1 = 0ull;
                fma2(acc0, q2[0], k2a);
                fma2(acc1, q2[1], k2b);
                fma2(acc0, q2[2], k2c);
                fma2(acc1, q2[3], k2d);
                float part = hsum2(acc0) + hsum2(acc1);
                part += __shfl_xor_sync(0xffffffffu, part, 1);
                part += __shfl_xor_sync(0xffffffffu, part, 2);
                part += __shfl_xor_sync(0xffffffffu, part, 4);
                if (sub == 0) {
                    bool valid = (gy >= 0 && gy < HH && gx >= 0 && gx < WW);
                    sw[p * SWS + dy * 7 + dx] = valid ? part * 0.125f : -1e30f;
                }
            }
        }
    }
    __syncthreads();   // all sq/sk reads done -> safe to overwrite with Wv

    // ---- Phase 3: issue Wv copy (group B); softmax -> transposed sw2 ----
    for (int i = t; i < 4096; i += 512)
        cpasync16(wvs + i * 4, Wv + i * 4, 16);
    asm volatile("cp.async.commit_group;");

    if (t < 64) {
        const int ppx = t & 7;
        float* r = sw + t * SWS;
        float m = r[0];
#pragma unroll
        for (int n = 1; n < 49; n++) m = fmaxf(m, r[n]);
        float e[49]; float sum = 0.0f;
#pragma unroll
        for (int n = 0; n < 49; n++) { e[n] = __expf(r[n] - m); sum += e[n]; }
        float inv = 1.0f / sum;
#pragma unroll
        for (int n = 0; n < 49; n++) {
            int dy = n / 7, dx = n % 7;
            sw2[(dy * 14 + ppx + dx) * 64 + t] = e[n] * inv;
        }
    }
    asm volatile("cp.async.wait_group 1;");   // V halo (group A) complete
    __syncthreads();

    // ---- Phase 4: weighted V sum. thread = (4 pixels, 4 channels) ----
    // warp = fixed pixel group; pg = t>>5: row = pg>>1, half = pg&1
    const int cc   = t & 31;
    const int pg   = t >> 5;
    const int row  = pg >> 1;
    const int half = pg & 1;

    u64 acc4[4][2];
#pragma unroll
    for (int i = 0; i < 4; i++) { acc4[i][0] = 0ull; acc4[i][1] = 0ull; }

    for (int dy = 0; dy < 7; dy++) {
        const float* svrow = sv + (row + dy) * WIN * SVS + cc * 4;
        const float* wrow  = sw2 + (dy * 14) * 64 + row * 8 + half * 4;
#pragma unroll
        for (int wxi = 0; wxi < 10; wxi++) {
            const int wx = half * 4 + wxi;
            u64 v0, v1;
            lds2(v0, v1, svrow + wx * SVS);
            float4 w = *reinterpret_cast<const float4*>(wrow + wx * 64);
            u64 wj;
            wj = dup2(w.x); fma2(acc4[0][0], wj, v0); fma2(acc4[0][1], wj, v1);
            wj = dup2(w.y); fma2(acc4[1][0], wj, v0); fma2(acc4[1][1], wj, v1);
            wj = dup2(w.z); fma2(acc4[2][0], wj, v0); fma2(acc4[2][1], wj, v1);
            wj = dup2(w.w); fma2(acc4[3][0], wj, v0); fma2(acc4[3][1], wj, v1);
        }
    }
    __syncthreads();   // all sv reads done -> safe to overwrite with at

    // ---- Phase 5: store attention output to smem (at overlays sv) ----
#pragma unroll
    for (int i = 0; i < 4; i++) {
        int p = row * 8 + half * 4 + i;
        float2 lo = unpack2(acc4[i][0]);
        float2 hi = unpack2(acc4[i][1]);
        *reinterpret_cast<float4*>(at + p * ATS + cc * 4) =
            make_float4(lo.x, lo.y, hi.x, hi.y);
    }
    asm volatile("cp.async.wait_group 0;");   // Wv staged
    __syncthreads();

    // ---- Phase 6: out = relu(at @ Wv + bv). thread = (4 px, 4 cols) ----
    {
        const int pg6 = t >> 5;          // 0..15 -> 4 pixels each
        const int tc  = t & 31;          // 0..31 -> 4 cols each
        const int p0  = pg6 * 4;
        const int c0  = tc * 4;

        u64 acc[4][4];
#pragma unroll
        for (int i = 0; i < 4; i++)
#pragma unroll
            for (int j = 0; j < 4; j++) acc[i][j] = 0ull;

#pragma unroll 2
        for (int kb = 0; kb < 32; kb++) {
            u64 a2[4][2];
#pragma unroll
            for (int i = 0; i < 4; i++)
                lds2(a2[i][0], a2[i][1], at + (p0 + i) * ATS + kb * 4);

            const float* wr = wvs + kb * 4 * 128 + c0;
            float4 w0 = *reinterpret_cast<const float4*>(wr);
            float4 w1 = *reinterpret_cast<const float4*>(wr + 128);
            float4 w2 = *reinterpret_cast<const float4*>(wr + 256);
            float4 w3 = *reinterpret_cast<const float4*>(wr + 384);
            u64 wp[4][2];
            wp[0][0] = pack2(w0.x, w1.x); wp[0][1] = pack2(w2.x, w3.x);
            wp[1][0] = pack2(w0.y, w1.y); wp[1][1] = pack2(w2.y, w3.y);
            wp[2][0] = pack2(w0.z, w1.z); wp[2][1] = pack2(w2.z, w3.z);
            wp[3][0] = pack2(w0.w, w1.w); wp[3][1] = pack2(w2.w, w3.w);

#pragma unroll
            for (int i = 0; i < 4; i++)
#pragma unroll
                for (int j = 0; j < 4; j++) {
                    fma2(acc[i][j], a2[i][0], wp[j][0]);
                    fma2(acc[i][j], a2[i][1], wp[j][1]);
                }
        }

        float b4[4];
#pragma unroll
        for (int j = 0; j < 4; j++) b4[j] = bv[c0 + j];

#pragma unroll
        for (int i = 0; i < 4; i++) {
            int p  = p0 + i;
            int py = ty0 + (p >> 3), px = tx0 + (p & 7);
            float4 o;
            o.x = fmaxf(hsum2(acc[i][0]) + b4[0], 0.0f);
            o.y = fmaxf(hsum2(acc[i][1]) + b4[1], 0.0f);
            o.z = fmaxf(hsum2(acc[i][2]) + b4[2], 0.0f);
            o.w = fmaxf(hsum2(acc[i][3]) + b4[3], 0.0f);
            *reinterpret_cast<float4*>(
                out + ((size_t)(b * HH + py) * WW + px) * CC + c0) = o;
        }
    }
}

// ---------------------------------------------------------------------------
extern "C" void kernel_launch(void* const* d_in, const int* in_sizes, int n_in,
                              void* d_out, int out_size)
{
    const float* Q  = (const float*)d_in[0];
    const float* K  = (const float*)d_in[1];
    const float* V  = (const float*)d_in[2];
    const float* Wq = (const float*)d_in[3];
    const float* bq = (const float*)d_in[4];
    const float* Wk = (const float*)d_in[5];
    const float* bk = (const float*)d_in[6];
    const float* Wv = (const float*)d_in[7];
    const float* bv = (const float*)d_in[8];
    float* out = (float*)d_out;

    float *qp, *kp;
    cudaGetSymbolAddress((void**)&qp, g_q);
    cudaGetSymbolAddress((void**)&kp, g_k);

    const int smem_qk   = (128 * ASP + 128 * 64) * 4;   // 100,352 B
    const int smem_attn = SMEM_ATTN_FLOATS * 4;         // 212,608 B

    cudaFuncSetAttribute((const void*)gemm_qk_kernel,
                         cudaFuncAttributeMaxDynamicSharedMemorySize, smem_qk);
    cudaFuncSetAttribute((const void*)attn_fused_kernel,
                         cudaFuncAttributeMaxDynamicSharedMemorySize, smem_attn);

    // q/k projections: 288 CTAs, 2/SM, single wave
    gemm_qk_kernel<<<dim3(NPIX / 128, 2), 256, smem_qk>>>(Q, K, Wq, Wk, bq, bk, qp, kp);

    // fused attention + output projection
    dim3 agrid(WW / TS, HH / TS, BATCH);  // (12,12,2)
    attn_fused_kernel<<<agrid, 512, smem_attn>>>(qp, kp, V, Wv, bv, out);
}